// round 1
// baseline (speedup 1.0000x reference)
#include <cuda_runtime.h>
#include <cstdint>
#include <math.h>

typedef unsigned long long ull;

#define Nn  50000
#define Rr  8
#define Ee  200000
#define EDd 400000
#define TOT (Rr * Ee)

// ---------------- scratch (__device__ globals; no allocation) ----------------
__device__ __align__(16) float g_M [(size_t)Nn * 2048];  // GEMM outputs [N, R*dout]
__device__ __align__(16) float g_H [(size_t)Nn * 256];   // hidden after layer-A agg
__device__ __align__(16) float g_h2[(size_t)Nn * 128];
__device__ __align__(16) float g_h3[(size_t)Nn * 128];
__device__ __align__(16) float g_Qt[(size_t)Nn * 8];
__device__ __align__(16) float g_Qb[(size_t)Nn * 8];
__device__ int   g_deg_src[Rr * Nn];
__device__ int   g_deg_dst[Rr * Nn];
__device__ int   g_row_ptr[Nn + 1];
__device__ int   g_cursor [Nn];
__device__ int   g_epack  [TOT];   // src | (rel<<24)
__device__ float g_ew     [TOT];   // per-edge norm weight
__device__ int   g_blksum [256];
__device__ float g_bsum   [768];   // sum_r bias: [0:256) b2a, [256:384) b2b, [384:640) b3a, [640:768) b3b
__device__ float g_Wp     [512 * 8];
__device__ __align__(16) float g_cvec[8];

// ---------------- graph build ----------------
__global__ void k_zero_degs() {
    int i = blockIdx.x * blockDim.x + threadIdx.x;
    if (i < Rr * Nn) { g_deg_src[i] = 0; g_deg_dst[i] = 0; }
}

__global__ void k_count(const int* __restrict__ src, const int* __restrict__ dst) {
    int i = blockIdx.x * blockDim.x + threadIdx.x;
    if (i < TOT) {
        int r = i / Ee;
        atomicAdd(&g_deg_src[r * Nn + src[i]], 1);
        atomicAdd(&g_deg_dst[r * Nn + dst[i]], 1);
    }
}

// block-local exclusive scan of total in-degree (1024 items/block, 256 thr x 4)
__global__ void k_scan1() {
    __shared__ int sh[256];
    int b = blockIdx.x, t = threadIdx.x;
    int base = b * 1024 + t * 4;
    int v[4];
#pragma unroll
    for (int j = 0; j < 4; j++) {
        int idx = base + j, s = 0;
        if (idx < Nn) {
#pragma unroll
            for (int r = 0; r < Rr; r++) s += g_deg_dst[r * Nn + idx];
        }
        v[j] = s;
    }
    int tsum = v[0] + v[1] + v[2] + v[3];
    sh[t] = tsum;
    __syncthreads();
    for (int off = 1; off < 256; off <<= 1) {
        int x = (t >= off) ? sh[t - off] : 0;
        __syncthreads();
        sh[t] += x;
        __syncthreads();
    }
    int run = sh[t] - tsum;  // exclusive
#pragma unroll
    for (int j = 0; j < 4; j++) {
        int idx = base + j;
        if (idx < Nn) g_row_ptr[idx] = run;
        run += v[j];
    }
    if (t == 255) g_blksum[b] = sh[255];
}

__global__ void k_scan2(int nb) {
    if (threadIdx.x == 0 && blockIdx.x == 0) {
        int acc = 0;
        for (int i = 0; i < nb; i++) { int s = g_blksum[i]; g_blksum[i] = acc; acc += s; }
    }
}

__global__ void k_scan3() {
    int i = blockIdx.x * blockDim.x + threadIdx.x;
    if (i < Nn) {
        int v = g_row_ptr[i] + g_blksum[i / 1024];
        g_row_ptr[i] = v;
        g_cursor[i]  = v;
    }
    if (i == 0) g_row_ptr[Nn] = TOT;
}

__global__ void k_fill(const int* __restrict__ src, const int* __restrict__ dst) {
    int i = blockIdx.x * blockDim.x + threadIdx.x;
    if (i < TOT) {
        int r = i / Ee;
        int s = src[i], d = dst[i];
        int pos = atomicAdd(&g_cursor[d], 1);
        g_epack[pos] = s | (r << 24);
        g_ew[pos] = rsqrtf((float)g_deg_src[r * Nn + s]) *
                    rsqrtf((float)g_deg_dst[r * Nn + d]);
    }
}

__global__ void k_bsum(const float* __restrict__ b2a, const float* __restrict__ b2b,
                       const float* __restrict__ b3a, const float* __restrict__ b3b) {
    int t = blockIdx.x * blockDim.x + threadIdx.x;
    if (t < 256)      { float s = 0; for (int r = 0; r < Rr; r++) s += b2a[r * 256 + t];        g_bsum[t] = s; }
    else if (t < 384) { int j = t - 256; float s = 0; for (int r = 0; r < Rr; r++) s += b2b[r * 128 + j]; g_bsum[t] = s; }
    else if (t < 640) { int j = t - 384; float s = 0; for (int r = 0; r < Rr; r++) s += b3a[r * 256 + j]; g_bsum[t] = s; }
    else if (t < 768) { int j = t - 640; float s = 0; for (int r = 0; r < Rr; r++) s += b3b[r * 128 + j]; g_bsum[t] = s; }
}

// ---------------- fp32x2 GEMM: C[:, r*dout + n] = A[N,K] @ B[r][K,dout] ----------------
// BM=128, BN=64, BK=16, 256 threads, 8x4 outputs/thread packed as 4x4 f32x2 (pairs along M)
__global__ void __launch_bounds__(256) k_gemm(
    const float* __restrict__ A, int K,
    const float* __restrict__ B, int dout,
    float* __restrict__ C, int ldc)
{
    __shared__ float As[16][128];
    __shared__ float Bs[16][64];

    int r  = blockIdx.z;
    const float* Br = B + (size_t)r * K * dout;
    int m0 = blockIdx.y * 128;
    int n0 = blockIdx.x * 64;
    int tid = threadIdx.x;
    int tn = (tid & 15) * 4;
    int tm = (tid >> 4) * 8;

    ull acc[4][4];
#pragma unroll
    for (int i = 0; i < 4; i++)
#pragma unroll
        for (int j = 0; j < 4; j++) acc[i][j] = 0ULL;

    int nkt = (K + 15) / 16;
    for (int kt = 0; kt < nkt; kt++) {
        int k0 = kt * 16;
        // A tile: 512 float4 (2/thread), coalesced 64B-per-row, store transposed
#pragma unroll
        for (int it = 0; it < 2; it++) {
            int idx = tid + it * 256;
            int m   = idx >> 2;
            int kv  = (idx & 3) * 4;
            int gm  = m0 + m;
            int gk  = k0 + kv;
            float4 av = make_float4(0.f, 0.f, 0.f, 0.f);
            if (gm < Nn && gk + 3 < K)  // K is always a multiple of 4 here
                av = *(const float4*)(A + (size_t)gm * K + gk);
            As[kv + 0][m] = av.x;
            As[kv + 1][m] = av.y;
            As[kv + 2][m] = av.z;
            As[kv + 3][m] = av.w;
        }
        // B tile: 256 float4 (1/thread)
        {
            int k  = tid >> 4;
            int nv = (tid & 15) * 4;
            float4 bv = make_float4(0.f, 0.f, 0.f, 0.f);
            if (k0 + k < K)
                bv = *(const float4*)(Br + (size_t)(k0 + k) * dout + n0 + nv);
            *(float4*)&Bs[k][nv] = bv;
        }
        __syncthreads();
#pragma unroll
        for (int k = 0; k < 16; k++) {
            const ull* ap = (const ull*)&As[k][tm];   // pairs of M-rows, 8B aligned
            ull a2[4];
            a2[0] = ap[0]; a2[1] = ap[1]; a2[2] = ap[2]; a2[3] = ap[3];
            float4 b = *(const float4*)&Bs[k][tn];
            ull bb[4];
            asm("mov.b64 %0, {%1, %1};" : "=l"(bb[0]) : "f"(b.x));
            asm("mov.b64 %0, {%1, %1};" : "=l"(bb[1]) : "f"(b.y));
            asm("mov.b64 %0, {%1, %1};" : "=l"(bb[2]) : "f"(b.z));
            asm("mov.b64 %0, {%1, %1};" : "=l"(bb[3]) : "f"(b.w));
#pragma unroll
            for (int i = 0; i < 4; i++)
#pragma unroll
                for (int j = 0; j < 4; j++)
                    asm("fma.rn.f32x2 %0, %1, %2, %0;"
                        : "+l"(acc[i][j]) : "l"(a2[i]), "l"(bb[j]));
        }
        __syncthreads();
    }

    size_t colbase = (size_t)r * dout + n0 + tn;
#pragma unroll
    for (int i = 0; i < 4; i++) {
        float lo[4], hi[4];
#pragma unroll
        for (int j = 0; j < 4; j++) {
            float l, h;
            asm("mov.b64 {%0, %1}, %2;" : "=f"(l), "=f"(h) : "l"(acc[i][j]));
            lo[j] = l; hi[j] = h;
        }
        int gm = m0 + tm + 2 * i;
        if (gm < Nn)
            *(float4*)(C + (size_t)gm * ldc + colbase) = make_float4(lo[0], lo[1], lo[2], lo[3]);
        if (gm + 1 < Nn)
            *(float4*)(C + (size_t)(gm + 1) * ldc + colbase) = make_float4(hi[0], hi[1], hi[2], hi[3]);
    }
}

// ---------------- CSR aggregation: out[v][t] = bsum[t] + sum_e w_e * M[s_e][r_e*dout + t] ----------------
__global__ void k_agg(const float* __restrict__ M, int ld, int dout,
                      const float* __restrict__ bsum, float* __restrict__ out, int relu)
{
    int v = blockIdx.x;
    int t = threadIdx.x;  // blockDim.x == dout
    int p0 = g_row_ptr[v], p1 = g_row_ptr[v + 1];
    float a0 = 0.f, a1 = 0.f, a2 = 0.f, a3 = 0.f;
    int p = p0;
    for (; p + 3 < p1; p += 4) {
        int   pk0 = g_epack[p],     pk1 = g_epack[p + 1];
        int   pk2 = g_epack[p + 2], pk3 = g_epack[p + 3];
        float w0 = g_ew[p],     w1 = g_ew[p + 1];
        float w2 = g_ew[p + 2], w3 = g_ew[p + 3];
        float m0 = __ldg(&M[(size_t)(pk0 & 0xFFFFFF) * ld + (pk0 >> 24) * dout + t]);
        float m1 = __ldg(&M[(size_t)(pk1 & 0xFFFFFF) * ld + (pk1 >> 24) * dout + t]);
        float m2 = __ldg(&M[(size_t)(pk2 & 0xFFFFFF) * ld + (pk2 >> 24) * dout + t]);
        float m3 = __ldg(&M[(size_t)(pk3 & 0xFFFFFF) * ld + (pk3 >> 24) * dout + t]);
        a0 = fmaf(w0, m0, a0);
        a1 = fmaf(w1, m1, a1);
        a2 = fmaf(w2, m2, a2);
        a3 = fmaf(w3, m3, a3);
    }
    for (; p < p1; p++) {
        int pk = g_epack[p];
        a0 = fmaf(g_ew[p], __ldg(&M[(size_t)(pk & 0xFFFFFF) * ld + (pk >> 24) * dout + t]), a0);
    }
    float acc = bsum[t] + (a0 + a1) + (a2 + a3);
    if (relu) acc = fmaxf(acc, 0.f);
    out[(size_t)v * dout + t] = acc;
}

// ---------------- decoder: Wp = Wp1@Wp2, cvec = bp1@Wp2 + bp2 ----------------
__global__ void k_wp(const float* __restrict__ Wp1, const float* __restrict__ bp1,
                     const float* __restrict__ Wp2, const float* __restrict__ bp2)
{
    int idx = blockIdx.x * blockDim.x + threadIdx.x;
    if (idx >= 513 * 8) return;
    int i = idx >> 3, c = idx & 7;
    if (i < 512) {
        float s = 0.f;
        for (int j = 0; j < 256; j++) s = fmaf(Wp1[i * 256 + j], Wp2[j * 8 + c], s);
        g_Wp[i * 8 + c] = s;
    } else {
        float s = bp2[c];
        for (int j = 0; j < 256; j++) s = fmaf(bp1[j], Wp2[j * 8 + c], s);
        g_cvec[c] = s;
    }
}

// Qt[n] = feat[n] @ Wp[0:256], Qb[n] = feat[n] @ Wp[256:512], feat = [h2 | h3]
__global__ void k_q() {
    __shared__ float sWp[512 * 8];
    for (int i = threadIdx.x; i < 512 * 8; i += blockDim.x) sWp[i] = g_Wp[i];
    __syncthreads();
    int n = blockIdx.x * blockDim.x + threadIdx.x;
    if (n >= Nn) return;
    float qt[8], qb[8];
#pragma unroll
    for (int c = 0; c < 8; c++) { qt[c] = 0.f; qb[c] = 0.f; }
    const float* h2 = &g_h2[(size_t)n * 128];
    const float* h3 = &g_h3[(size_t)n * 128];
    for (int j = 0; j < 128; j++) {
        float x2 = h2[j], x3 = h3[j];
#pragma unroll
        for (int c = 0; c < 8; c++) {
            qt[c] = fmaf(x2, sWp[j * 8 + c],         qt[c]);
            qt[c] = fmaf(x3, sWp[(128 + j) * 8 + c], qt[c]);
            qb[c] = fmaf(x2, sWp[(256 + j) * 8 + c], qb[c]);
            qb[c] = fmaf(x3, sWp[(384 + j) * 8 + c], qb[c]);
        }
    }
#pragma unroll
    for (int c = 0; c < 8; c++) {
        g_Qt[(size_t)n * 8 + c] = qt[c];
        g_Qb[(size_t)n * 8 + c] = qb[c];
    }
}

__global__ void k_edge(const int* __restrict__ ds, const int* __restrict__ dd,
                       float* __restrict__ out)
{
    int e = blockIdx.x * blockDim.x + threadIdx.x;
    if (e >= EDd) return;
    int s = ds[e], d = dd[e];
    const float4* qt = (const float4*)&g_Qt[(size_t)s * 8];
    const float4* qb = (const float4*)&g_Qb[(size_t)d * 8];
    const float4* cv = (const float4*)g_cvec;
    float4 t0 = qt[0], t1 = qt[1], b0 = qb[0], b1 = qb[1], c0 = cv[0], c1 = cv[1];
    float4 o0 = make_float4(t0.x + b0.x + c0.x, t0.y + b0.y + c0.y,
                            t0.z + b0.z + c0.z, t0.w + b0.w + c0.w);
    float4 o1 = make_float4(t1.x + b1.x + c1.x, t1.y + b1.y + c1.y,
                            t1.z + b1.z + c1.z, t1.w + b1.w + c1.w);
    float4* o = (float4*)out;
    o[2 * e]     = o0;
    o[2 * e + 1] = o1;
}

// ---------------- launcher ----------------
extern "C" void kernel_launch(void* const* d_in, const int* in_sizes, int n_in,
                              void* d_out, int out_size)
{
    const float* x2  = (const float*)d_in[0];
    const float* x3  = (const float*)d_in[1];
    const int*   src = (const int*)d_in[2];
    const int*   dst = (const int*)d_in[3];
    const int*   dsr = (const int*)d_in[4];
    const int*   dds = (const int*)d_in[5];
    const float* W2a = (const float*)d_in[6];
    const float* b2a = (const float*)d_in[7];
    const float* W2b = (const float*)d_in[8];
    const float* b2b = (const float*)d_in[9];
    const float* W3a = (const float*)d_in[10];
    const float* b3a = (const float*)d_in[11];
    const float* W3b = (const float*)d_in[12];
    const float* b3b = (const float*)d_in[13];
    const float* Wp1 = (const float*)d_in[14];
    const float* bp1 = (const float*)d_in[15];
    const float* Wp2 = (const float*)d_in[16];
    const float* bp2 = (const float*)d_in[17];
    float* out = (float*)d_out;

    void *pM, *pH, *ph2, *ph3, *pBsum;
    cudaGetSymbolAddress(&pM, g_M);
    cudaGetSymbolAddress(&pH, g_H);
    cudaGetSymbolAddress(&ph2, g_h2);
    cudaGetSymbolAddress(&ph3, g_h3);
    cudaGetSymbolAddress(&pBsum, g_bsum);
    float* M    = (float*)pM;
    float* H    = (float*)pH;
    float* h2   = (float*)ph2;
    float* h3   = (float*)ph3;
    float* bsum = (float*)pBsum;

    // graph build (reused by all 4 propagations)
    k_zero_degs<<<(Rr * Nn + 255) / 256, 256>>>();
    k_count<<<(TOT + 255) / 256, 256>>>(src, dst);
    k_scan1<<<(Nn + 1023) / 1024, 256>>>();
    k_scan2<<<1, 32>>>((Nn + 1023) / 1024);
    k_scan3<<<(Nn + 255) / 256, 256>>>();
    k_fill<<<(TOT + 255) / 256, 256>>>(src, dst);
    k_bsum<<<3, 256>>>(b2a, b2b, b3a, b3b);
    k_wp<<<(513 * 8 + 127) / 128, 128>>>(Wp1, bp1, Wp2, bp2);

    dim3 gA(4, (Nn + 127) / 128, 8);
    dim3 gB(2, (Nn + 127) / 128, 8);

    // tower 2 (node2_features, K=256)
    k_gemm<<<gA, 256>>>(x2, 256, W2a, 256, M, 2048);
    k_agg<<<Nn, 256>>>(M, 2048, 256, bsum + 0, H, 1);
    k_gemm<<<gB, 256>>>(H, 256, W2b, 128, M, 1024);
    k_agg<<<Nn, 128>>>(M, 1024, 128, bsum + 256, h2, 0);

    // tower 3 (mpnn_features, K=300)
    k_gemm<<<gA, 256>>>(x3, 300, W3a, 256, M, 2048);
    k_agg<<<Nn, 256>>>(M, 2048, 256, bsum + 384, H, 1);
    k_gemm<<<gB, 256>>>(H, 256, W3b, 128, M, 1024);
    k_agg<<<Nn, 128>>>(M, 1024, 128, bsum + 640, h3, 0);

    // decoder
    k_q<<<(Nn + 255) / 256, 256>>>();
    k_edge<<<(EDd + 255) / 256, 256>>>(dsr, dds, out);
}

// round 3
// speedup vs baseline: 1.6504x; 1.6504x over previous
#include <cuda_runtime.h>
#include <cuda_bf16.h>
#include <cstdint>
#include <math.h>

typedef unsigned long long ull;

#define Nn  50000
#define Rr  8
#define Ee  200000
#define EDd 400000
#define TOT (Rr * Ee)

// ---------------- scratch (__device__ globals; no allocation) ----------------
__device__ __align__(16) float g_M [(size_t)Nn * 2048];  // GEMM outputs [N, R*dout]
__device__ __align__(16) __nv_bfloat16 g_Xh[(size_t)Nn * 320];
__device__ __align__(16) __nv_bfloat16 g_Xl[(size_t)Nn * 320];
__device__ __align__(16) __nv_bfloat16 g_Hh[(size_t)Nn * 256];
__device__ __align__(16) __nv_bfloat16 g_Hl[(size_t)Nn * 256];
__device__ __align__(16) __nv_bfloat16 g_Wh[8 * 256 * 320];  // B^T [r][dout][Kpad]
__device__ __align__(16) __nv_bfloat16 g_Wl[8 * 256 * 320];
__device__ __align__(16) float g_h2[(size_t)Nn * 128];
__device__ __align__(16) float g_h3[(size_t)Nn * 128];
__device__ __align__(16) float g_Qt[(size_t)Nn * 8];
__device__ __align__(16) float g_Qb[(size_t)Nn * 8];
__device__ int   g_deg_src[Rr * Nn];
__device__ int   g_deg_dst[Rr * Nn];
__device__ int   g_row_ptr[Nn + 1];
__device__ int   g_cursor [Nn];
__device__ int   g_epack  [TOT];   // src | (rel<<24)
__device__ float g_ew     [TOT];   // per-edge norm weight
__device__ int   g_blksum [256];
__device__ float g_bsum   [768];
__device__ float g_Wp     [512 * 8];
__device__ __align__(16) float g_cvec[8];

// ---------------- helpers ----------------
__device__ __forceinline__ uint32_t smem_u32(const void* p) {
    uint32_t a;
    asm("{ .reg .u64 t; cvta.to.shared.u64 t, %1; cvt.u32.u64 %0, t; }" : "=r"(a) : "l"(p));
    return a;
}
#define SWZ(b) ((b) ^ (((b) >> 3) & 0x70))

__device__ __forceinline__ void ldmx4(uint32_t* r, uint32_t addr) {
    asm volatile("ldmatrix.sync.aligned.m8n8.x4.shared.b16 {%0,%1,%2,%3}, [%4];"
        : "=r"(r[0]), "=r"(r[1]), "=r"(r[2]), "=r"(r[3]) : "r"(addr));
}
__device__ __forceinline__ void mma16816(float* c, const uint32_t* a, const uint32_t* b) {
    asm volatile(
        "mma.sync.aligned.m16n8k16.row.col.f32.bf16.bf16.f32 "
        "{%0,%1,%2,%3}, {%4,%5,%6,%7}, {%8,%9}, {%0,%1,%2,%3};"
        : "+f"(c[0]), "+f"(c[1]), "+f"(c[2]), "+f"(c[3])
        : "r"(a[0]), "r"(a[1]), "r"(a[2]), "r"(a[3]), "r"(b[0]), "r"(b[1]));
}

// ---------------- graph build ----------------
__global__ void k_zero_degs() {
    int i = blockIdx.x * blockDim.x + threadIdx.x;
    if (i < Rr * Nn) { g_deg_src[i] = 0; g_deg_dst[i] = 0; }
}
__global__ void k_count(const int* __restrict__ src, const int* __restrict__ dst) {
    int i = blockIdx.x * blockDim.x + threadIdx.x;
    if (i < TOT) {
        int r = i / Ee;
        atomicAdd(&g_deg_src[r * Nn + src[i]], 1);
        atomicAdd(&g_deg_dst[r * Nn + dst[i]], 1);
    }
}
__global__ void k_scan1() {
    __shared__ int sh[256];
    int b = blockIdx.x, t = threadIdx.x;
    int base = b * 1024 + t * 4;
    int v[4];
#pragma unroll
    for (int j = 0; j < 4; j++) {
        int idx = base + j, s = 0;
        if (idx < Nn) {
#pragma unroll
            for (int r = 0; r < Rr; r++) s += g_deg_dst[r * Nn + idx];
        }
        v[j] = s;
    }
    int tsum = v[0] + v[1] + v[2] + v[3];
    sh[t] = tsum;
    __syncthreads();
    for (int off = 1; off < 256; off <<= 1) {
        int x = (t >= off) ? sh[t - off] : 0;
        __syncthreads();
        sh[t] += x;
        __syncthreads();
    }
    int run = sh[t] - tsum;
#pragma unroll
    for (int j = 0; j < 4; j++) {
        int idx = base + j;
        if (idx < Nn) g_row_ptr[idx] = run;
        run += v[j];
    }
    if (t == 255) g_blksum[b] = sh[255];
}
__global__ void k_scan2(int nb) {
    if (threadIdx.x == 0 && blockIdx.x == 0) {
        int acc = 0;
        for (int i = 0; i < nb; i++) { int s = g_blksum[i]; g_blksum[i] = acc; acc += s; }
    }
}
__global__ void k_scan3() {
    int i = blockIdx.x * blockDim.x + threadIdx.x;
    if (i < Nn) {
        int v = g_row_ptr[i] + g_blksum[i / 1024];
        g_row_ptr[i] = v;
        g_cursor[i]  = v;
    }
    if (i == 0) g_row_ptr[Nn] = TOT;
}
__global__ void k_fill(const int* __restrict__ src, const int* __restrict__ dst) {
    int i = blockIdx.x * blockDim.x + threadIdx.x;
    if (i < TOT) {
        int r = i / Ee;
        int s = src[i], d = dst[i];
        int pos = atomicAdd(&g_cursor[d], 1);
        g_epack[pos] = s | (r << 24);
        g_ew[pos] = rsqrtf((float)g_deg_src[r * Nn + s]) *
                    rsqrtf((float)g_deg_dst[r * Nn + d]);
    }
}
__global__ void k_bsum(const float* __restrict__ b2a, const float* __restrict__ b2b,
                       const float* __restrict__ b3a, const float* __restrict__ b3b) {
    int t = blockIdx.x * blockDim.x + threadIdx.x;
    if (t < 256)      { float s = 0; for (int r = 0; r < Rr; r++) s += b2a[r * 256 + t];        g_bsum[t] = s; }
    else if (t < 384) { int j = t - 256; float s = 0; for (int r = 0; r < Rr; r++) s += b2b[r * 128 + j]; g_bsum[t] = s; }
    else if (t < 640) { int j = t - 384; float s = 0; for (int r = 0; r < Rr; r++) s += b3a[r * 256 + j]; g_bsum[t] = s; }
    else if (t < 768) { int j = t - 640; float s = 0; for (int r = 0; r < Rr; r++) s += b3b[r * 128 + j]; g_bsum[t] = s; }
}

// ---------------- bf16 hi/lo splits ----------------
__global__ void k_split_x(const float* __restrict__ X, int K, int Kpad,
                          __nv_bfloat16* __restrict__ hi, __nv_bfloat16* __restrict__ lo, int n)
{
    long long i = (long long)blockIdx.x * blockDim.x + threadIdx.x;
    if (i >= (long long)n * Kpad) return;
    int row = (int)(i / Kpad), k = (int)(i % Kpad);
    float v = (k < K) ? X[(size_t)row * K + k] : 0.f;
    __nv_bfloat16 h = __float2bfloat16(v);
    hi[i] = h;
    lo[i] = __float2bfloat16(v - __bfloat162float(h));
}

// weights: W [r][K][dout] fp32 -> B^T hi/lo [r][dout][Kpad]
__global__ void k_split_w(const float* __restrict__ W, int K, int Kpad, int dout,
                          __nv_bfloat16* __restrict__ hi, __nv_bfloat16* __restrict__ lo)
{
    int i = blockIdx.x * blockDim.x + threadIdx.x;
    if (i >= Rr * dout * Kpad) return;
    int k = i % Kpad;
    int n = (i / Kpad) % dout;
    int r = i / (Kpad * dout);
    float v = (k < K) ? W[((size_t)r * K + k) * dout + n] : 0.f;
    __nv_bfloat16 h = __float2bfloat16(v);
    hi[i] = h;
    lo[i] = __float2bfloat16(v - __bfloat162float(h));
}

// ---------------- HMMA split-bf16 GEMM ----------------
// C[m, r*dout + n] = A[m,:].B[r][n,:]   A:[Nn,Kpad] hi/lo, B:[r][dout][Kpad] hi/lo
// BM=128, BN=64, BK=64. 256 threads = 8 warps (4M x 2N), warp tile 32x32.
__global__ void __launch_bounds__(256) k_mma(
    const __nv_bfloat16* __restrict__ Ah, const __nv_bfloat16* __restrict__ Al, int Kpad,
    const __nv_bfloat16* __restrict__ Bh, const __nv_bfloat16* __restrict__ Bl, int dout,
    float* __restrict__ C, int ldc)
{
    __shared__ __nv_bfloat16 smAh[128 * 64];
    __shared__ __nv_bfloat16 smAl[128 * 64];
    __shared__ __nv_bfloat16 smBh[64 * 64];
    __shared__ __nv_bfloat16 smBl[64 * 64];
    char* cAh = (char*)smAh;
    char* cAl = (char*)smAl;
    char* cBh = (char*)smBh;
    char* cBl = (char*)smBl;
    uint32_t uAh = smem_u32(smAh), uAl = smem_u32(smAl);
    uint32_t uBh = smem_u32(smBh), uBl = smem_u32(smBl);

    int tid = threadIdx.x;
    int warp = tid >> 5, lane = tid & 31;
    int wm = warp & 3, wn = warp >> 2;
    int r  = blockIdx.z;
    int m0 = blockIdx.y * 128;
    int n0 = blockIdx.x * 64;

    const __nv_bfloat16* Bhr = Bh + ((size_t)r * dout + n0) * Kpad;
    const __nv_bfloat16* Blr = Bl + ((size_t)r * dout + n0) * Kpad;

    float acc[2][4][4];
#pragma unroll
    for (int i = 0; i < 2; i++)
#pragma unroll
        for (int j = 0; j < 4; j++)
#pragma unroll
            for (int q = 0; q < 4; q++) acc[i][j][q] = 0.f;

    // ldmatrix lane addressing (constant across chunks except k-step col)
    int a_row = (lane & 15);             // 0..15 within m16 tile
    int a_cb  = (lane >> 4) << 4;        // 0 or 16 bytes (k half)
    int b_row = (lane & 7) + ((lane >> 4) << 3);  // n within 16-wide pair
    int b_cb  = ((lane >> 3) & 1) << 4;           // 0 or 16 bytes

    int nch = Kpad >> 6;
    for (int c = 0; c < nch; c++) {
        long long acol = (long long)(c << 6);
        __syncthreads();
        // A: 128 rows x 128B (hi & lo), 4 iters x 256 thr, 8 float4 per row
#pragma unroll
        for (int i = 0; i < 4; i++) {
            int idx = i * 256 + tid;
            int row = idx >> 3, j = idx & 7;
            int gm  = m0 + row;
            float4 vh = make_float4(0.f, 0.f, 0.f, 0.f), vl = vh;
            if (gm < Nn) {
                vh = *(const float4*)(Ah + (size_t)gm * Kpad + acol + j * 8);
                vl = *(const float4*)(Al + (size_t)gm * Kpad + acol + j * 8);
            }
            uint32_t o = SWZ((uint32_t)(row * 128 + j * 16));
            *(float4*)(cAh + o) = vh;
            *(float4*)(cAl + o) = vl;
        }
        // B: 64 rows x 128B (hi & lo), 2 iters
#pragma unroll
        for (int i = 0; i < 2; i++) {
            int idx = i * 256 + tid;
            int row = idx >> 3, j = idx & 7;
            float4 vh = *(const float4*)(Bhr + (size_t)row * Kpad + acol + j * 8);
            float4 vl = *(const float4*)(Blr + (size_t)row * Kpad + acol + j * 8);
            uint32_t o = SWZ((uint32_t)(row * 128 + j * 16));
            *(float4*)(cBh + o) = vh;
            *(float4*)(cBl + o) = vl;
        }
        __syncthreads();

#pragma unroll
        for (int ks = 0; ks < 4; ks++) {
            uint32_t ah[2][4], al[2][4], bh[4][2], bl[4][2];
#pragma unroll
            for (int mt = 0; mt < 2; mt++) {
                uint32_t off = SWZ((uint32_t)((wm * 32 + mt * 16 + a_row) * 128 + ks * 32 + a_cb));
                ldmx4(ah[mt], uAh + off);
                ldmx4(al[mt], uAl + off);
            }
#pragma unroll
            for (int np = 0; np < 2; np++) {
                uint32_t off = SWZ((uint32_t)((wn * 32 + np * 16 + b_row) * 128 + ks * 32 + b_cb));
                uint32_t th[4], tl[4];
                ldmx4(th, uBh + off);
                ldmx4(tl, uBl + off);
                bh[np * 2][0] = th[0]; bh[np * 2][1] = th[1];
                bh[np * 2 + 1][0] = th[2]; bh[np * 2 + 1][1] = th[3];
                bl[np * 2][0] = tl[0]; bl[np * 2][1] = tl[1];
                bl[np * 2 + 1][0] = tl[2]; bl[np * 2 + 1][1] = tl[3];
            }
#pragma unroll
            for (int mt = 0; mt < 2; mt++)
#pragma unroll
                for (int nt = 0; nt < 4; nt++) {
                    mma16816(acc[mt][nt], ah[mt], bh[nt]);
                    mma16816(acc[mt][nt], ah[mt], bl[nt]);
                    mma16816(acc[mt][nt], al[mt], bh[nt]);
                }
        }
    }

    // epilogue
    size_t colbase = (size_t)r * dout + n0 + wn * 32;
    int lrow = lane >> 2, lcol = (lane & 3) * 2;
#pragma unroll
    for (int mt = 0; mt < 2; mt++) {
        int gm0 = m0 + wm * 32 + mt * 16 + lrow;
#pragma unroll
        for (int nt = 0; nt < 4; nt++) {
            float* cp = C + colbase + nt * 8 + lcol;
            if (gm0 < Nn)
                *(float2*)(cp + (size_t)gm0 * ldc) = make_float2(acc[mt][nt][0], acc[mt][nt][1]);
            if (gm0 + 8 < Nn)
                *(float2*)(cp + (size_t)(gm0 + 8) * ldc) = make_float2(acc[mt][nt][2], acc[mt][nt][3]);
        }
    }
}

// ---------------- CSR aggregation ----------------
__device__ __forceinline__ float agg_row(const float* __restrict__ M, int ld, int dout,
                                         int v, int t)
{
    int p0 = g_row_ptr[v], p1 = g_row_ptr[v + 1];
    float a0 = 0.f, a1 = 0.f, a2 = 0.f, a3 = 0.f;
    int p = p0;
    for (; p + 3 < p1; p += 4) {
        int   pk0 = g_epack[p],     pk1 = g_epack[p + 1];
        int   pk2 = g_epack[p + 2], pk3 = g_epack[p + 3];
        float w0 = g_ew[p],     w1 = g_ew[p + 1];
        float w2 = g_ew[p + 2], w3 = g_ew[p + 3];
        float m0 = __ldg(&M[(size_t)(pk0 & 0xFFFFFF) * ld + (pk0 >> 24) * dout + t]);
        float m1 = __ldg(&M[(size_t)(pk1 & 0xFFFFFF) * ld + (pk1 >> 24) * dout + t]);
        float m2 = __ldg(&M[(size_t)(pk2 & 0xFFFFFF) * ld + (pk2 >> 24) * dout + t]);
        float m3 = __ldg(&M[(size_t)(pk3 & 0xFFFFFF) * ld + (pk3 >> 24) * dout + t]);
        a0 = fmaf(w0, m0, a0);
        a1 = fmaf(w1, m1, a1);
        a2 = fmaf(w2, m2, a2);
        a3 = fmaf(w3, m3, a3);
    }
    for (; p < p1; p++) {
        int pk = g_epack[p];
        a0 = fmaf(g_ew[p], __ldg(&M[(size_t)(pk & 0xFFFFFF) * ld + (pk >> 24) * dout + t]), a0);
    }
    return (a0 + a1) + (a2 + a3);
}

__global__ void k_agg_relu_split(const float* __restrict__ M, int ld, int dout,
                                 const float* __restrict__ bsum,
                                 __nv_bfloat16* __restrict__ Hh, __nv_bfloat16* __restrict__ Hl)
{
    int v = blockIdx.x, t = threadIdx.x;
    float acc = fmaxf(bsum[t] + agg_row(M, ld, dout, v, t), 0.f);
    __nv_bfloat16 h = __float2bfloat16(acc);
    Hh[(size_t)v * dout + t] = h;
    Hl[(size_t)v * dout + t] = __float2bfloat16(acc - __bfloat162float(h));
}

__global__ void k_agg_f32(const float* __restrict__ M, int ld, int dout,
                          const float* __restrict__ bsum, float* __restrict__ out)
{
    int v = blockIdx.x, t = threadIdx.x;
    out[(size_t)v * dout + t] = bsum[t] + agg_row(M, ld, dout, v, t);
}

// ---------------- decoder ----------------
__global__ void k_wp(const float* __restrict__ Wp1, const float* __restrict__ bp1,
                     const float* __restrict__ Wp2, const float* __restrict__ bp2)
{
    int idx = blockIdx.x * blockDim.x + threadIdx.x;
    if (idx >= 513 * 8) return;
    int i = idx >> 3, c = idx & 7;
    if (i < 512) {
        float s = 0.f;
        for (int j = 0; j < 256; j++) s = fmaf(Wp1[i * 256 + j], Wp2[j * 8 + c], s);
        g_Wp[i * 8 + c] = s;
    } else {
        float s = bp2[c];
        for (int j = 0; j < 256; j++) s = fmaf(bp1[j], Wp2[j * 8 + c], s);
        g_cvec[c] = s;
    }
}

__global__ void k_q() {
    __shared__ float sWp[512 * 8];
    for (int i = threadIdx.x; i < 512 * 8; i += blockDim.x) sWp[i] = g_Wp[i];
    __syncthreads();
    int n = blockIdx.x * blockDim.x + threadIdx.x;
    if (n >= Nn) return;
    float qt[8], qb[8];
#pragma unroll
    for (int c = 0; c < 8; c++) { qt[c] = 0.f; qb[c] = 0.f; }
    const float* h2 = &g_h2[(size_t)n * 128];
    const float* h3 = &g_h3[(size_t)n * 128];
    for (int j = 0; j < 128; j++) {
        float x2 = h2[j], x3 = h3[j];
#pragma unroll
        for (int c = 0; c < 8; c++) {
            qt[c] = fmaf(x2, sWp[j * 8 + c],         qt[c]);
            qt[c] = fmaf(x3, sWp[(128 + j) * 8 + c], qt[c]);
            qb[c] = fmaf(x2, sWp[(256 + j) * 8 + c], qb[c]);
            qb[c] = fmaf(x3, sWp[(384 + j) * 8 + c], qb[c]);
        }
    }
#pragma unroll
    for (int c = 0; c < 8; c++) {
        g_Qt[(size_t)n * 8 + c] = qt[c];
        g_Qb[(size_t)n * 8 + c] = qb[c];
    }
}

__global__ void k_edge(const int* __restrict__ ds, const int* __restrict__ dd,
                       float* __restrict__ out)
{
    int e = blockIdx.x * blockDim.x + threadIdx.x;
    if (e >= EDd) return;
    int s = ds[e], d = dd[e];
    const float4* qt = (const float4*)&g_Qt[(size_t)s * 8];
    const float4* qb = (const float4*)&g_Qb[(size_t)d * 8];
    const float4* cv = (const float4*)g_cvec;
    float4 t0 = qt[0], t1 = qt[1], b0 = qb[0], b1 = qb[1], c0 = cv[0], c1 = cv[1];
    float4 o0 = make_float4(t0.x + b0.x + c0.x, t0.y + b0.y + c0.y,
                            t0.z + b0.z + c0.z, t0.w + b0.w + c0.w);
    float4 o1 = make_float4(t1.x + b1.x + c1.x, t1.y + b1.y + c1.y,
                            t1.z + b1.z + c1.z, t1.w + b1.w + c1.w);
    float4* o = (float4*)out;
    o[2 * e]     = o0;
    o[2 * e + 1] = o1;
}

// ---------------- launcher ----------------
extern "C" void kernel_launch(void* const* d_in, const int* in_sizes, int n_in,
                              void* d_out, int out_size)
{
    const float* x2  = (const float*)d_in[0];
    const float* x3  = (const float*)d_in[1];
    const int*   src = (const int*)d_in[2];
    const int*   dst = (const int*)d_in[3];
    const int*   dsr = (const int*)d_in[4];
    const int*   dds = (const int*)d_in[5];
    const float* W2a = (const float*)d_in[6];
    const float* b2a = (const float*)d_in[7];
    const float* W2b = (const float*)d_in[8];
    const float* b2b = (const float*)d_in[9];
    const float* W3a = (const float*)d_in[10];
    const float* b3a = (const float*)d_in[11];
    const float* W3b = (const float*)d_in[12];
    const float* b3b = (const float*)d_in[13];
    const float* Wp1 = (const float*)d_in[14];
    const float* bp1 = (const float*)d_in[15];
    const float* Wp2 = (const float*)d_in[16];
    const float* bp2 = (const float*)d_in[17];
    float* out = (float*)d_out;

    void *pM, *ph2, *ph3, *pBsum, *pXh, *pXl, *pHh, *pHl, *pWh, *pWl;
    cudaGetSymbolAddress(&pM, g_M);
    cudaGetSymbolAddress(&ph2, g_h2);
    cudaGetSymbolAddress(&ph3, g_h3);
    cudaGetSymbolAddress(&pBsum, g_bsum);
    cudaGetSymbolAddress(&pXh, g_Xh);
    cudaGetSymbolAddress(&pXl, g_Xl);
    cudaGetSymbolAddress(&pHh, g_Hh);
    cudaGetSymbolAddress(&pHl, g_Hl);
    cudaGetSymbolAddress(&pWh, g_Wh);
    cudaGetSymbolAddress(&pWl, g_Wl);
    float* M = (float*)pM;
    float* h2 = (float*)ph2;
    float* h3 = (float*)ph3;
    float* bsum = (float*)pBsum;
    __nv_bfloat16* Xh = (__nv_bfloat16*)pXh;
    __nv_bfloat16* Xl = (__nv_bfloat16*)pXl;
    __nv_bfloat16* Hh = (__nv_bfloat16*)pHh;
    __nv_bfloat16* Hl = (__nv_bfloat16*)pHl;
    __nv_bfloat16* Wh = (__nv_bfloat16*)pWh;
    __nv_bfloat16* Wl = (__nv_bfloat16*)pWl;

    dim3 gA(4, (Nn + 127) / 128, 8);   // dout=256
    dim3 gB(2, (Nn + 127) / 128, 8);   // dout=128

    // Launch order arranged so ncu (-s 5 -c 1) profiles the first big MMA kernel.
    k_split_x<<<((long long)Nn * 256 + 255) / 256, 256>>>(x2, 256, 256, Xh, Xl, Nn);  // 0
    k_split_w<<<(Rr * 256 * 256 + 255) / 256, 256>>>(W2a, 256, 256, 256, Wh, Wl);     // 1
    k_zero_degs<<<(Rr * Nn + 255) / 256, 256>>>();                                    // 2
    k_count<<<(TOT + 255) / 256, 256>>>(src, dst);                                    // 3
    k_scan1<<<(Nn + 1023) / 1024, 256>>>();                                           // 4
    k_mma<<<gA, 256>>>(Xh, Xl, 256, Wh, Wl, 256, M, 2048);                            // 5 <- profiled
    k_scan2<<<1, 32>>>((Nn + 1023) / 1024);                                           // 6
    k_scan3<<<(Nn + 255) / 256, 256>>>();                                             // 7
    k_fill<<<(TOT + 255) / 256, 256>>>(src, dst);                                     // 8
    k_bsum<<<3, 256>>>(b2a, b2b, b3a, b3b);                                           // 9

    // tower 2 rest
    k_agg_relu_split<<<Nn, 256>>>(M, 2048, 256, bsum + 0, Hh, Hl);
    k_split_w<<<(Rr * 128 * 256 + 255) / 256, 256>>>(W2b, 256, 256, 128, Wh, Wl);
    k_mma<<<gB, 256>>>(Hh, Hl, 256, Wh, Wl, 128, M, 1024);
    k_agg_f32<<<Nn, 128>>>(M, 1024, 128, bsum + 256, h2);

    // tower 3 (K=300 -> pad 320)
    k_split_x<<<((long long)Nn * 320 + 255) / 256, 256>>>(x3, 300, 320, Xh, Xl, Nn);
    k_split_w<<<(Rr * 256 * 320 + 255) / 256, 256>>>(W3a, 300, 320, 256, Wh, Wl);
    k_mma<<<gA, 256>>>(Xh, Xl, 320, Wh, Wl, 256, M, 2048);
    k_agg_relu_split<<<Nn, 256>>>(M, 2048, 256, bsum + 384, Hh, Hl);
    k_split_w<<<(Rr * 128 * 256 + 255) / 256, 256>>>(W3b, 256, 256, 128, Wh, Wl);
    k_mma<<<gB, 256>>>(Hh, Hl, 256, Wh, Wl, 128, M, 1024);
    k_agg_f32<<<Nn, 128>>>(M, 1024, 128, bsum + 640, h3);

    // decoder
    k_wp<<<(513 * 8 + 127) / 128, 128>>>(Wp1, bp1, Wp2, bp2);
    k_q<<<(Nn + 255) / 256, 256>>>();
    k_edge<<<(EDd + 255) / 256, 256>>>(dsr, dds, out);
}

// round 4
// speedup vs baseline: 2.1247x; 1.2874x over previous
#include <cuda_runtime.h>
#include <cuda_fp16.h>
#include <cstdint>
#include <math.h>

#define Nn  50000
#define Rr  8
#define Ee  200000
#define EDd 400000
#define TOT (Rr * Ee)

// ---------------- scratch (__device__ globals; no allocation) ----------------
__device__ __align__(16) __half g_M16[(size_t)Nn * 2048];  // GEMM outputs [N, R*dout] fp16
__device__ __align__(16) __half g_X16[(size_t)Nn * 320];   // activations fp16
__device__ __align__(16) __half g_H16[(size_t)Nn * 256];   // hidden fp16
__device__ __align__(16) __half g_Wh [8 * 256 * 320];      // W^T hi [r][dout][Kpad]
__device__ __align__(16) __half g_Wl [8 * 256 * 320];      // W^T lo
__device__ __align__(16) float g_h2[(size_t)Nn * 128];
__device__ __align__(16) float g_h3[(size_t)Nn * 128];
__device__ __align__(16) float g_Qt[(size_t)Nn * 8];
__device__ __align__(16) float g_Qb[(size_t)Nn * 8];
__device__ int   g_deg_src[Rr * Nn];
__device__ int   g_deg_dst[Rr * Nn];
__device__ int   g_row_ptr[Nn + 1];
__device__ int   g_cursor [Nn];
__device__ int   g_epack  [TOT];   // src | (rel<<24)
__device__ float g_ew     [TOT];   // per-edge norm weight
__device__ int   g_blksum [256];
__device__ float g_bsum   [768];
__device__ float g_Wp     [512 * 8];
__device__ __align__(16) float g_cvec[8];

// ---------------- helpers ----------------
__device__ __forceinline__ uint32_t smem_u32(const void* p) {
    uint32_t a;
    asm("{ .reg .u64 t; cvta.to.shared.u64 t, %1; cvt.u32.u64 %0, t; }" : "=r"(a) : "l"(p));
    return a;
}
#define SWZ(b) ((b) ^ (((b) >> 3) & 0x70))

__device__ __forceinline__ void ldmx4(uint32_t* r, uint32_t addr) {
    asm volatile("ldmatrix.sync.aligned.m8n8.x4.shared.b16 {%0,%1,%2,%3}, [%4];"
        : "=r"(r[0]), "=r"(r[1]), "=r"(r[2]), "=r"(r[3]) : "r"(addr));
}
__device__ __forceinline__ void mma16816(float* c, const uint32_t* a, const uint32_t* b) {
    asm volatile(
        "mma.sync.aligned.m16n8k16.row.col.f32.f16.f16.f32 "
        "{%0,%1,%2,%3}, {%4,%5,%6,%7}, {%8,%9}, {%0,%1,%2,%3};"
        : "+f"(c[0]), "+f"(c[1]), "+f"(c[2]), "+f"(c[3])
        : "r"(a[0]), "r"(a[1]), "r"(a[2]), "r"(a[3]), "r"(b[0]), "r"(b[1]));
}
__device__ __forceinline__ void cpa16(uint32_t d, const void* s) {
    asm volatile("cp.async.cg.shared.global [%0], [%1], 16;" :: "r"(d), "l"(s));
}
#define CP_COMMIT() asm volatile("cp.async.commit_group;" ::: "memory")

// ---------------- graph build ----------------
__global__ void k_zero_degs() {
    int i = blockIdx.x * blockDim.x + threadIdx.x;
    if (i < Rr * Nn) { g_deg_src[i] = 0; g_deg_dst[i] = 0; }
}
__global__ void k_count(const int* __restrict__ src, const int* __restrict__ dst) {
    int i = blockIdx.x * blockDim.x + threadIdx.x;
    if (i < TOT) {
        int r = i / Ee;
        atomicAdd(&g_deg_src[r * Nn + src[i]], 1);
        atomicAdd(&g_deg_dst[r * Nn + dst[i]], 1);
    }
}
__global__ void k_scan1() {
    __shared__ int sh[256];
    int b = blockIdx.x, t = threadIdx.x;
    int base = b * 1024 + t * 4;
    int v[4];
#pragma unroll
    for (int j = 0; j < 4; j++) {
        int idx = base + j, s = 0;
        if (idx < Nn) {
#pragma unroll
            for (int r = 0; r < Rr; r++) s += g_deg_dst[r * Nn + idx];
        }
        v[j] = s;
    }
    int tsum = v[0] + v[1] + v[2] + v[3];
    sh[t] = tsum;
    __syncthreads();
    for (int off = 1; off < 256; off <<= 1) {
        int x = (t >= off) ? sh[t - off] : 0;
        __syncthreads();
        sh[t] += x;
        __syncthreads();
    }
    int run = sh[t] - tsum;
#pragma unroll
    for (int j = 0; j < 4; j++) {
        int idx = base + j;
        if (idx < Nn) g_row_ptr[idx] = run;
        run += v[j];
    }
    if (t == 255) g_blksum[b] = sh[255];
}
__global__ void k_scan2(int nb) {
    if (threadIdx.x == 0 && blockIdx.x == 0) {
        int acc = 0;
        for (int i = 0; i < nb; i++) { int s = g_blksum[i]; g_blksum[i] = acc; acc += s; }
    }
}
__global__ void k_scan3() {
    int i = blockIdx.x * blockDim.x + threadIdx.x;
    if (i < Nn) {
        int v = g_row_ptr[i] + g_blksum[i / 1024];
        g_row_ptr[i] = v;
        g_cursor[i]  = v;
    }
    if (i == 0) g_row_ptr[Nn] = TOT;
}
__global__ void k_fill(const int* __restrict__ src, const int* __restrict__ dst) {
    int i = blockIdx.x * blockDim.x + threadIdx.x;
    if (i < TOT) {
        int r = i / Ee;
        int s = src[i], d = dst[i];
        int pos = atomicAdd(&g_cursor[d], 1);
        g_epack[pos] = s | (r << 24);
        g_ew[pos] = rsqrtf((float)g_deg_src[r * Nn + s]) *
                    rsqrtf((float)g_deg_dst[r * Nn + d]);
    }
}
__global__ void k_bsum(const float* __restrict__ b2a, const float* __restrict__ b2b,
                       const float* __restrict__ b3a, const float* __restrict__ b3b) {
    int t = blockIdx.x * blockDim.x + threadIdx.x;
    if (t < 256)      { float s = 0; for (int r = 0; r < Rr; r++) s += b2a[r * 256 + t];        g_bsum[t] = s; }
    else if (t < 384) { int j = t - 256; float s = 0; for (int r = 0; r < Rr; r++) s += b2b[r * 128 + j]; g_bsum[t] = s; }
    else if (t < 640) { int j = t - 384; float s = 0; for (int r = 0; r < Rr; r++) s += b3a[r * 256 + j]; g_bsum[t] = s; }
    else if (t < 768) { int j = t - 640; float s = 0; for (int r = 0; r < Rr; r++) s += b3b[r * 128 + j]; g_bsum[t] = s; }
}

// ---------------- fp16 conversions ----------------
__global__ void k_split_x16(const float* __restrict__ X, int K, int Kpad,
                            __half* __restrict__ out, int n)
{
    long long i = (long long)blockIdx.x * blockDim.x + threadIdx.x;
    if (i >= (long long)n * Kpad) return;
    int row = (int)(i / Kpad), k = (int)(i % Kpad);
    float v = (k < K) ? X[(size_t)row * K + k] : 0.f;
    out[i] = __float2half(v);
}

// weights: W [r][K][dout] fp32 -> W^T hi/lo [r][dout][Kpad] fp16
__global__ void k_split_w16(const float* __restrict__ W, int K, int Kpad, int dout,
                            __half* __restrict__ hi, __half* __restrict__ lo)
{
    int i = blockIdx.x * blockDim.x + threadIdx.x;
    if (i >= Rr * dout * Kpad) return;
    int k = i % Kpad;
    int n = (i / Kpad) % dout;
    int r = i / (Kpad * dout);
    float v = (k < K) ? W[((size_t)r * K + k) * dout + n] : 0.f;
    __half h = __float2half(v);
    hi[i] = h;
    lo[i] = __float2half(v - __half2float(h));
}

// ---------------- HMMA fp16 2-term GEMM, cp.async double-buffered ----------------
// C[m, r*dout + n] = A[m,:] . (Wh[r][n,:] + Wl[r][n,:])
// BM=128, BN=64, BK=64. 256 threads = 8 warps (4M x 2N), warp tile 32x32.
#define OFF_A  0
#define OFF_BH 16384
#define OFF_BL 24576
#define STAGE  32768

__global__ void __launch_bounds__(256, 2) k_mma(
    const __half* __restrict__ A, int Kpad,
    const __half* __restrict__ Bh, const __half* __restrict__ Bl, int dout,
    __half* __restrict__ C, int ldc)
{
    extern __shared__ char smem[];
    uint32_t sb = smem_u32(smem);

    int tid = threadIdx.x;
    int warp = tid >> 5, lane = tid & 31;
    int wm = warp & 3, wn = warp >> 2;
    int r  = blockIdx.z;
    int m0 = blockIdx.y * 128;
    int n0 = blockIdx.x * 64;

    const __half* Bhr = Bh + ((size_t)r * dout + n0) * Kpad;
    const __half* Blr = Bl + ((size_t)r * dout + n0) * Kpad;

    float acc[2][4][4];
#pragma unroll
    for (int i = 0; i < 2; i++)
#pragma unroll
        for (int j = 0; j < 4; j++)
#pragma unroll
            for (int q = 0; q < 4; q++) acc[i][j][q] = 0.f;

    // per-thread load indices (8 cp.async of 16B per stage)
    int lrowA = tid >> 3;          // 0..31 base row step 32 (4 iters)
    int ljA   = tid & 7;
    // ldmatrix lane addressing
    int a_row = (lane & 15);
    int a_cb  = (lane >> 4) << 4;
    int b_row = (lane & 7) + ((lane >> 4) << 3);
    int b_cb  = ((lane >> 3) & 1) << 4;

    int nch = Kpad >> 6;

    // ---- load stage 0 ----
    {
        uint32_t base = sb;
#pragma unroll
        for (int i = 0; i < 4; i++) {
            int row = i * 32 + lrowA;
            int gm  = m0 + row; if (gm > Nn - 1) gm = Nn - 1;
            cpa16(base + OFF_A + SWZ((uint32_t)(row * 128 + ljA * 16)),
                  A + (size_t)gm * Kpad + ljA * 8);
        }
#pragma unroll
        for (int i = 0; i < 2; i++) {
            int row = i * 32 + lrowA;
            uint32_t o = SWZ((uint32_t)(row * 128 + ljA * 16));
            cpa16(base + OFF_BH + o, Bhr + (size_t)row * Kpad + ljA * 8);
            cpa16(base + OFF_BL + o, Blr + (size_t)row * Kpad + ljA * 8);
        }
        CP_COMMIT();
    }

    for (int c = 0; c < nch; c++) {
        int buf = c & 1;
        if (c + 1 < nch) {
            uint32_t base = sb + (buf ^ 1) * STAGE;
            long long acol = (long long)((c + 1) << 6);
#pragma unroll
            for (int i = 0; i < 4; i++) {
                int row = i * 32 + lrowA;
                int gm  = m0 + row; if (gm > Nn - 1) gm = Nn - 1;
                cpa16(base + OFF_A + SWZ((uint32_t)(row * 128 + ljA * 16)),
                      A + (size_t)gm * Kpad + acol + ljA * 8);
            }
#pragma unroll
            for (int i = 0; i < 2; i++) {
                int row = i * 32 + lrowA;
                uint32_t o = SWZ((uint32_t)(row * 128 + ljA * 16));
                cpa16(base + OFF_BH + o, Bhr + (size_t)row * Kpad + acol + ljA * 8);
                cpa16(base + OFF_BL + o, Blr + (size_t)row * Kpad + acol + ljA * 8);
            }
            CP_COMMIT();
            asm volatile("cp.async.wait_group 1;" ::: "memory");
        } else {
            asm volatile("cp.async.wait_group 0;" ::: "memory");
        }
        __syncthreads();

        uint32_t uA  = sb + buf * STAGE + OFF_A;
        uint32_t uBH = sb + buf * STAGE + OFF_BH;
        uint32_t uBL = sb + buf * STAGE + OFF_BL;
#pragma unroll
        for (int ks = 0; ks < 4; ks++) {
            uint32_t ah[2][4], bh[4][2], bl[4][2];
#pragma unroll
            for (int mt = 0; mt < 2; mt++) {
                uint32_t off = SWZ((uint32_t)((wm * 32 + mt * 16 + a_row) * 128 + ks * 32 + a_cb));
                ldmx4(ah[mt], uA + off);
            }
#pragma unroll
            for (int np = 0; np < 2; np++) {
                uint32_t off = SWZ((uint32_t)((wn * 32 + np * 16 + b_row) * 128 + ks * 32 + b_cb));
                uint32_t th[4], tl[4];
                ldmx4(th, uBH + off);
                ldmx4(tl, uBL + off);
                bh[np * 2][0] = th[0]; bh[np * 2][1] = th[1];
                bh[np * 2 + 1][0] = th[2]; bh[np * 2 + 1][1] = th[3];
                bl[np * 2][0] = tl[0]; bl[np * 2][1] = tl[1];
                bl[np * 2 + 1][0] = tl[2]; bl[np * 2 + 1][1] = tl[3];
            }
#pragma unroll
            for (int mt = 0; mt < 2; mt++)
#pragma unroll
                for (int nt = 0; nt < 4; nt++) {
                    mma16816(acc[mt][nt], ah[mt], bh[nt]);
                    mma16816(acc[mt][nt], ah[mt], bl[nt]);
                }
        }
        __syncthreads();
    }

    // epilogue: fp32 acc -> fp16
    size_t colbase = (size_t)r * dout + n0 + wn * 32;
    int lrow = lane >> 2, lcol = (lane & 3) * 2;
#pragma unroll
    for (int mt = 0; mt < 2; mt++) {
        int gm0 = m0 + wm * 32 + mt * 16 + lrow;
#pragma unroll
        for (int nt = 0; nt < 4; nt++) {
            __half* cp = C + colbase + nt * 8 + lcol;
            if (gm0 < Nn)
                *(__half2*)(cp + (size_t)gm0 * ldc) =
                    __floats2half2_rn(acc[mt][nt][0], acc[mt][nt][1]);
            if (gm0 + 8 < Nn)
                *(__half2*)(cp + (size_t)(gm0 + 8) * ldc) =
                    __floats2half2_rn(acc[mt][nt][2], acc[mt][nt][3]);
        }
    }
}

// ---------------- CSR aggregation (fp16 messages, fp32 accum) ----------------
__device__ __forceinline__ float agg_row(const __half* __restrict__ M, int ld, int dout,
                                         int v, int t)
{
    int p0 = g_row_ptr[v], p1 = g_row_ptr[v + 1];
    float a0 = 0.f, a1 = 0.f, a2 = 0.f, a3 = 0.f;
    int p = p0;
    for (; p + 3 < p1; p += 4) {
        int   pk0 = g_epack[p],     pk1 = g_epack[p + 1];
        int   pk2 = g_epack[p + 2], pk3 = g_epack[p + 3];
        float w0 = g_ew[p],     w1 = g_ew[p + 1];
        float w2 = g_ew[p + 2], w3 = g_ew[p + 3];
        float m0 = __half2float(__ldg(&M[(size_t)(pk0 & 0xFFFFFF) * ld + (pk0 >> 24) * dout + t]));
        float m1 = __half2float(__ldg(&M[(size_t)(pk1 & 0xFFFFFF) * ld + (pk1 >> 24) * dout + t]));
        float m2 = __half2float(__ldg(&M[(size_t)(pk2 & 0xFFFFFF) * ld + (pk2 >> 24) * dout + t]));
        float m3 = __half2float(__ldg(&M[(size_t)(pk3 & 0xFFFFFF) * ld + (pk3 >> 24) * dout + t]));
        a0 = fmaf(w0, m0, a0);
        a1 = fmaf(w1, m1, a1);
        a2 = fmaf(w2, m2, a2);
        a3 = fmaf(w3, m3, a3);
    }
    for (; p < p1; p++) {
        int pk = g_epack[p];
        a0 = fmaf(g_ew[p],
                  __half2float(__ldg(&M[(size_t)(pk & 0xFFFFFF) * ld + (pk >> 24) * dout + t])),
                  a0);
    }
    return (a0 + a1) + (a2 + a3);
}

__global__ void k_agg_relu_f16(const __half* __restrict__ M, int ld, int dout,
                               const float* __restrict__ bsum, __half* __restrict__ H)
{
    int v = blockIdx.x, t = threadIdx.x;
    float acc = fmaxf(bsum[t] + agg_row(M, ld, dout, v, t), 0.f);
    H[(size_t)v * dout + t] = __float2half(acc);
}

__global__ void k_agg_f32(const __half* __restrict__ M, int ld, int dout,
                          const float* __restrict__ bsum, float* __restrict__ out)
{
    int v = blockIdx.x, t = threadIdx.x;
    out[(size_t)v * dout + t] = bsum[t] + agg_row(M, ld, dout, v, t);
}

// ---------------- decoder ----------------
__global__ void k_wp(const float* __restrict__ Wp1, const float* __restrict__ bp1,
                     const float* __restrict__ Wp2, const float* __restrict__ bp2)
{
    int idx = blockIdx.x * blockDim.x + threadIdx.x;
    if (idx >= 513 * 8) return;
    int i = idx >> 3, c = idx & 7;
    if (i < 512) {
        float s = 0.f;
        for (int j = 0; j < 256; j++) s = fmaf(Wp1[i * 256 + j], Wp2[j * 8 + c], s);
        g_Wp[i * 8 + c] = s;
    } else {
        float s = bp2[c];
        for (int j = 0; j < 256; j++) s = fmaf(bp1[j], Wp2[j * 8 + c], s);
        g_cvec[c] = s;
    }
}

__global__ void k_q() {
    __shared__ float sWp[512 * 8];
    for (int i = threadIdx.x; i < 512 * 8; i += blockDim.x) sWp[i] = g_Wp[i];
    __syncthreads();
    int n = blockIdx.x * blockDim.x + threadIdx.x;
    if (n >= Nn) return;
    float qt[8], qb[8];
#pragma unroll
    for (int c = 0; c < 8; c++) { qt[c] = 0.f; qb[c] = 0.f; }
    const float* h2 = &g_h2[(size_t)n * 128];
    const float* h3 = &g_h3[(size_t)n * 128];
    for (int j = 0; j < 128; j++) {
        float x2 = h2[j], x3 = h3[j];
#pragma unroll
        for (int c = 0; c < 8; c++) {
            qt[c] = fmaf(x2, sWp[j * 8 + c],         qt[c]);
            qt[c] = fmaf(x3, sWp[(128 + j) * 8 + c], qt[c]);
            qb[c] = fmaf(x2, sWp[(256 + j) * 8 + c], qb[c]);
            qb[c] = fmaf(x3, sWp[(384 + j) * 8 + c], qb[c]);
        }
    }
#pragma unroll
    for (int c = 0; c < 8; c++) {
        g_Qt[(size_t)n * 8 + c] = qt[c];
        g_Qb[(size_t)n * 8 + c] = qb[c];
    }
}

__global__ void k_edge(const int* __restrict__ ds, const int* __restrict__ dd,
                       float* __restrict__ out)
{
    int e = blockIdx.x * blockDim.x + threadIdx.x;
    if (e >= EDd) return;
    int s = ds[e], d = dd[e];
    const float4* qt = (const float4*)&g_Qt[(size_t)s * 8];
    const float4* qb = (const float4*)&g_Qb[(size_t)d * 8];
    const float4* cv = (const float4*)g_cvec;
    float4 t0 = qt[0], t1 = qt[1], b0 = qb[0], b1 = qb[1], c0 = cv[0], c1 = cv[1];
    float4 o0 = make_float4(t0.x + b0.x + c0.x, t0.y + b0.y + c0.y,
                            t0.z + b0.z + c0.z, t0.w + b0.w + c0.w);
    float4 o1 = make_float4(t1.x + b1.x + c1.x, t1.y + b1.y + c1.y,
                            t1.z + b1.z + c1.z, t1.w + b1.w + c1.w);
    float4* o = (float4*)out;
    o[2 * e]     = o0;
    o[2 * e + 1] = o1;
}

// ---------------- launcher ----------------
extern "C" void kernel_launch(void* const* d_in, const int* in_sizes, int n_in,
                              void* d_out, int out_size)
{
    const float* x2  = (const float*)d_in[0];
    const float* x3  = (const float*)d_in[1];
    const int*   src = (const int*)d_in[2];
    const int*   dst = (const int*)d_in[3];
    const int*   dsr = (const int*)d_in[4];
    const int*   dds = (const int*)d_in[5];
    const float* W2a = (const float*)d_in[6];
    const float* b2a = (const float*)d_in[7];
    const float* W2b = (const float*)d_in[8];
    const float* b2b = (const float*)d_in[9];
    const float* W3a = (const float*)d_in[10];
    const float* b3a = (const float*)d_in[11];
    const float* W3b = (const float*)d_in[12];
    const float* b3b = (const float*)d_in[13];
    const float* Wp1 = (const float*)d_in[14];
    const float* bp1 = (const float*)d_in[15];
    const float* Wp2 = (const float*)d_in[16];
    const float* bp2 = (const float*)d_in[17];
    float* out = (float*)d_out;

    const int SMEM_MMA = 2 * STAGE;  // 65536
    cudaFuncSetAttribute(k_mma, cudaFuncAttributeMaxDynamicSharedMemorySize, SMEM_MMA);

    void *pM, *ph2, *ph3, *pBsum, *pX, *pH, *pWh, *pWl;
    cudaGetSymbolAddress(&pM, g_M16);
    cudaGetSymbolAddress(&ph2, g_h2);
    cudaGetSymbolAddress(&ph3, g_h3);
    cudaGetSymbolAddress(&pBsum, g_bsum);
    cudaGetSymbolAddress(&pX, g_X16);
    cudaGetSymbolAddress(&pH, g_H16);
    cudaGetSymbolAddress(&pWh, g_Wh);
    cudaGetSymbolAddress(&pWl, g_Wl);
    __half* M  = (__half*)pM;
    float*  h2 = (float*)ph2;
    float*  h3 = (float*)ph3;
    float*  bsum = (float*)pBsum;
    __half* X  = (__half*)pX;
    __half* H  = (__half*)pH;
    __half* Wh = (__half*)pWh;
    __half* Wl = (__half*)pWl;

    dim3 gA(4, (Nn + 127) / 128, 8);   // dout=256
    dim3 gB(2, (Nn + 127) / 128, 8);   // dout=128

    // launch index 3 gets profiled -> k_mma there
    k_split_x16<<<((long long)Nn * 256 + 255) / 256, 256>>>(x2, 256, 256, X, Nn);     // 0
    k_split_w16<<<(Rr * 256 * 256 + 255) / 256, 256>>>(W2a, 256, 256, 256, Wh, Wl);   // 1
    k_zero_degs<<<(Rr * Nn + 255) / 256, 256>>>();                                    // 2
    k_mma<<<gA, 256, SMEM_MMA>>>(X, 256, Wh, Wl, 256, M, 2048);                       // 3 <- profiled
    k_count<<<(TOT + 255) / 256, 256>>>(src, dst);                                    // 4
    k_scan1<<<(Nn + 1023) / 1024, 256>>>();                                           // 5
    k_scan2<<<1, 32>>>((Nn + 1023) / 1024);                                           // 6
    k_scan3<<<(Nn + 255) / 256, 256>>>();                                             // 7
    k_fill<<<(TOT + 255) / 256, 256>>>(src, dst);                                     // 8
    k_bsum<<<3, 256>>>(b2a, b2b, b3a, b3b);                                           // 9

    // tower 2 rest
    k_agg_relu_f16<<<Nn, 256>>>(M, 2048, 256, bsum + 0, H);
    k_split_w16<<<(Rr * 128 * 256 + 255) / 256, 256>>>(W2b, 256, 256, 128, Wh, Wl);
    k_mma<<<gB, 256, SMEM_MMA>>>(H, 256, Wh, Wl, 128, M, 1024);
    k_agg_f32<<<Nn, 128>>>(M, 1024, 128, bsum + 256, h2);

    // tower 3 (K=300 -> pad 320)
    k_split_x16<<<((long long)Nn * 320 + 255) / 256, 256>>>(x3, 300, 320, X, Nn);
    k_split_w16<<<(Rr * 256 * 320 + 255) / 256, 256>>>(W3a, 300, 320, 256, Wh, Wl);
    k_mma<<<gA, 256, SMEM_MMA>>>(X, 320, Wh, Wl, 256, M, 2048);
    k_agg_relu_f16<<<Nn, 256>>>(M, 2048, 256, bsum + 384, H);
    k_split_w16<<<(Rr * 128 * 256 + 255) / 256, 256>>>(W3b, 256, 256, 128, Wh, Wl);
    k_mma<<<gB, 256, SMEM_MMA>>>(H, 256, Wh, Wl, 128, M, 1024);
    k_agg_f32<<<Nn, 128>>>(M, 1024, 128, bsum + 640, h3);

    // decoder
    k_wp<<<(513 * 8 + 127) / 128, 128>>>(Wp1, bp1, Wp2, bp2);
    k_q<<<(Nn + 255) / 256, 256>>>();
    k_edge<<<(EDd + 255) / 256, 256>>>(dsr, dds, out);
}